// round 9
// baseline (speedup 1.0000x reference)
#include <cuda_runtime.h>

// Problem constants (T=512, B=32, A=64, N=128, H=8)
#define TPB   256
#define ADIM  64
#define NDIM  128
#define HDIM  8
#define TILES 4     // (t,b) pairs per block -> amortize weight LDS 4x

__global__ __launch_bounds__(TPB, 3)
void attn_fused_kernel(const float* __restrict__ agent,
                       const float* __restrict__ Wq, const float* __restrict__ bq,
                       const float* __restrict__ Wk, const float* __restrict__ bk,
                       float* __restrict__ out)
{
    __shared__ float sW[2][HDIM][NDIM];     // [0]=Wq^T, [1]=Wk^T  (sW[m][h][n])
    __shared__ float sb[2][HDIM];           // [0]=bq, [1]=bk
    __shared__ float qsm[TILES][ADIM * HDIM];   // q[a][h] at a*8+h
    __shared__ float ksm[TILES][ADIM * HDIM];   // k flat row-major; att reads ksm[h*64+a]

    const int tid = threadIdx.x;
    const long long tb0 = (long long)blockIdx.x * TILES;

    // ---- weights (transposed) + biases into smem ----
    for (int i = tid; i < NDIM * HDIM; i += TPB) {
        int n = i >> 3, h = i & 7;
        sW[0][h][n] = Wq[i];
        sW[1][h][n] = Wk[i];
    }
    if (tid < HDIM)        sb[0][tid] = bq[tid];
    else if (tid < 2*HDIM) sb[1][tid - HDIM] = bk[tid - HDIM];
    __syncthreads();

    // =========== phase 1: Q/K projection for 4 tiles, two passes (q, then k) ===========
    // Same lane map / address pattern / full-unroll body as the 366us kernel, but only
    // ONE matrix's accumulators live at a time: acc[4][8] = 32 regs instead of 64.
    {
        const int r = tid >> 2;   // agent row 0..63
        const int c = tid & 3;    // chunk within row

        const float4* srow[TILES];
        #pragma unroll
        for (int t = 0; t < TILES; t++)
            srow[t] = reinterpret_cast<const float4*>(
                agent + (tb0 + t) * (long long)(ADIM * NDIM) + (long long)r * NDIM);

        const int b0 = c & 1;
        const int b1 = (c >> 1) & 1;
        const int hoff = b0 * 4 + b1 * 2;   // the two h-values this lane finally owns

        #pragma unroll 1
        for (int m = 0; m < 2; m++) {       // m=0 -> q, m=1 -> k  (sequential passes)
            float acc[TILES][HDIM];
            #pragma unroll
            for (int t = 0; t < TILES; t++)
                #pragma unroll
                for (int h = 0; h < HDIM; h++) acc[t][h] = 0.f;

            #pragma unroll
            for (int k = 0; k < 8; k++) {
                float4 s[TILES];
                #pragma unroll
                for (int t = 0; t < TILES; t++) s[t] = srow[t][c + 4 * k];

                const int nb = (c + 4 * k) * 4;
                #pragma unroll
                for (int h = 0; h < HDIM; h++) {
                    const float4 w = *reinterpret_cast<const float4*>(&sW[m][h][nb]);
                    #pragma unroll
                    for (int t = 0; t < TILES; t++)
                        acc[t][h] += s[t].x * w.x + s[t].y * w.y + s[t].z * w.z + s[t].w * w.w;
                }
            }

            // Halving butterfly across the 4 lanes of this row.
            // Stage 1 (xor 1): b0 picks h-half. Stage 2 (xor 2): b1 picks h-quarter.
            float* dst = m ? ksm[0] : qsm[0];
            const int stride = ADIM * HDIM;
            #pragma unroll
            for (int t = 0; t < TILES; t++) {
                float v[4];
                #pragma unroll
                for (int i = 0; i < 4; i++) {
                    float sent = b0 ? acc[t][i] : acc[t][i + 4];
                    float recv = __shfl_xor_sync(0xffffffffu, sent, 1);
                    v[i] = (b0 ? acc[t][i + 4] : acc[t][i]) + recv;
                }
                #pragma unroll
                for (int i = 0; i < 2; i++) {
                    float sent = b1 ? v[i] : v[i + 2];
                    float recv = __shfl_xor_sync(0xffffffffu, sent, 2);
                    float f = (b1 ? v[i + 2] : v[i]) + recv;
                    dst[t * stride + r * HDIM + hoff + i] = f + sb[m][hoff + i];
                }
            }
        }
    }
    __syncthreads();

    // =========== phase 2: logits + softmax + off-diag store ===========
    // thread = (row-pair, 8-column chunk)
    {
        const int rp = tid >> 3;        // 0..31
        const int cc = tid & 7;         // column chunk 0..7
        const int r0 = rp * 2, r1 = r0 + 1;

        #pragma unroll
        for (int t = 0; t < TILES; t++) {
            float q0[HDIM], q1[HDIM];
            {
                float4 a = *reinterpret_cast<const float4*>(&qsm[t][r0 * HDIM]);
                float4 b = *reinterpret_cast<const float4*>(&qsm[t][r0 * HDIM + 4]);
                q0[0]=a.x; q0[1]=a.y; q0[2]=a.z; q0[3]=a.w;
                q0[4]=b.x; q0[5]=b.y; q0[6]=b.z; q0[7]=b.w;
                float4 e = *reinterpret_cast<const float4*>(&qsm[t][r1 * HDIM]);
                float4 d = *reinterpret_cast<const float4*>(&qsm[t][r1 * HDIM + 4]);
                q1[0]=e.x; q1[1]=e.y; q1[2]=e.z; q1[3]=e.w;
                q1[4]=d.x; q1[5]=d.y; q1[6]=d.z; q1[7]=d.w;
            }

            float a0[8], a1[8];
            #pragma unroll
            for (int i = 0; i < 8; i++) { a0[i] = 0.f; a1[i] = 0.f; }

            // att[r][a] = sum_h q[r][h] * kflat[h*64 + a]  (reshape semantics)
            #pragma unroll
            for (int h = 0; h < HDIM; h++) {
                const float4 ka = *reinterpret_cast<const float4*>(&ksm[t][h * ADIM + cc * 8]);
                const float4 kb = *reinterpret_cast<const float4*>(&ksm[t][h * ADIM + cc * 8 + 4]);
                const float x0 = q0[h], x1 = q1[h];
                a0[0] += x0 * ka.x; a0[1] += x0 * ka.y; a0[2] += x0 * ka.z; a0[3] += x0 * ka.w;
                a0[4] += x0 * kb.x; a0[5] += x0 * kb.y; a0[6] += x0 * kb.z; a0[7] += x0 * kb.w;
                a1[0] += x1 * ka.x; a1[1] += x1 * ka.y; a1[2] += x1 * ka.z; a1[3] += x1 * ka.w;
                a1[4] += x1 * kb.x; a1[5] += x1 * kb.y; a1[6] += x1 * kb.z; a1[7] += x1 * kb.w;
            }

            // softmax over 64 cols: 8 local + reduce over the 8 lanes of this row-pair
            float m0 = a0[0], m1 = a1[0];
            #pragma unroll
            for (int i = 1; i < 8; i++) { m0 = fmaxf(m0, a0[i]); m1 = fmaxf(m1, a1[i]); }
            #pragma unroll
            for (int s = 1; s < 8; s <<= 1) {
                m0 = fmaxf(m0, __shfl_xor_sync(0xffffffffu, m0, s));
                m1 = fmaxf(m1, __shfl_xor_sync(0xffffffffu, m1, s));
            }
            float s0 = 0.f, s1 = 0.f;
            #pragma unroll
            for (int i = 0; i < 8; i++) {
                a0[i] = __expf(a0[i] - m0); s0 += a0[i];
                a1[i] = __expf(a1[i] - m1); s1 += a1[i];
            }
            #pragma unroll
            for (int s = 1; s < 8; s <<= 1) {
                s0 += __shfl_xor_sync(0xffffffffu, s0, s);
                s1 += __shfl_xor_sync(0xffffffffu, s1, s);
            }
            const float inv0 = __frcp_rn(s0);
            const float inv1 = __frcp_rn(s1);

            // off-diagonal gather store: col a -> a (a<r) / a-1 (a>r), skip a==r
            const long long tb = tb0 + t;
            float* o0 = out + (tb * ADIM + r0) * (long long)(ADIM - 1);
            float* o1 = out + (tb * ADIM + r1) * (long long)(ADIM - 1);
            #pragma unroll
            for (int i = 0; i < 8; i++) {
                const int a = cc * 8 + i;
                if (a != r0) o0[a - (a > r0 ? 1 : 0)] = a0[i] * inv0;
                if (a != r1) o1[a - (a > r1 ? 1 : 0)] = a1[i] * inv1;
            }
        }
    }
}

extern "C" void kernel_launch(void* const* d_in, const int* in_sizes, int n_in,
                              void* d_out, int out_size)
{
    const float* agent = (const float*)d_in[0];
    const float* Wq    = (const float*)d_in[1];
    const float* bq    = (const float*)d_in[2];
    const float* Wk    = (const float*)d_in[3];
    const float* bk    = (const float*)d_in[4];
    float* out = (float*)d_out;

    const int T = 512, B = 32;
    attn_fused_kernel<<<(T * B) / TILES, TPB>>>(agent, Wq, bq, Wk, bk, out);
}

// round 10
// speedup vs baseline: 1.2574x; 1.2574x over previous
#include <cuda_runtime.h>

// Problem constants (T=512, B=32, A=64, N=128, H=8)
#define TPB   256
#define ADIM  64
#define NDIM  128
#define HDIM  8
#define TLOOP 4      // tiles processed sequentially per block (weight-LDS amortization)
#define WPAD  132    // padded row stride (floats): conflict-free + 16B-aligned (132*4=528=33*16)

__device__ __forceinline__ void fma2(unsigned long long& d,
                                     unsigned long long a,
                                     unsigned long long b) {
    // packed fp32x2 FMA (sm_103a); per-lane round-to-nearest == scalar FFMA
    asm("fma.rn.f32x2 %0, %1, %2, %0;" : "+l"(d) : "l"(a), "l"(b));
}

union U64F2 { unsigned long long u; float2 f; };

__global__ __launch_bounds__(TPB, 4)
void attn_fused_kernel(const float* __restrict__ agent,
                       const float* __restrict__ Wq, const float* __restrict__ bq,
                       const float* __restrict__ Wk, const float* __restrict__ bk,
                       float* __restrict__ out)
{
    __shared__ float sW[2][HDIM][WPAD];   // [0]=Wq^T, [1]=Wk^T  (sW[m][h][n])
    __shared__ float sb[2][HDIM];
    __shared__ float sA[ADIM][WPAD];      // staged agent tile (one tile at a time)
    __shared__ float qsm[ADIM * HDIM];    // q[a][h] at a*8+h
    __shared__ float ksm[ADIM * HDIM];    // k flat row-major; att reads ksm[h*64+a]

    const int tid = threadIdx.x;
    const long long tb0 = (long long)blockIdx.x * TLOOP;

    // ---- weights (transposed, padded) + biases into smem ----
    for (int i = tid; i < NDIM * HDIM; i += TPB) {
        int n = i >> 3, h = i & 7;
        sW[0][h][n] = Wq[i];
        sW[1][h][n] = Wk[i];
    }
    if (tid < HDIM)        sb[0][tid] = bq[tid];
    else if (tid < 2*HDIM) sb[1][tid - HDIM] = bk[tid - HDIM];
    // (first __syncthreads below orders these before any reads)

    const int r  = tid >> 2;        // row 0..63
    const int c  = tid & 3;         // quad lane
    const int h0 = 2 * c;           // h-pair owned by this lane
    const int h1 = 2 * c + 1;

    #pragma unroll 1
    for (int t = 0; t < TLOOP; t++) {
        // ====== stage agent tile (64x128 f32 = 32KB) into smem, fully coalesced ======
        const float4* g = reinterpret_cast<const float4*>(
            agent + (tb0 + t) * (long long)(ADIM * NDIM));
        #pragma unroll
        for (int j = 0; j < 8; j++) {
            const int idx = tid + j * TPB;          // float4 index 0..2047
            const int row = idx >> 5;               // 32 float4 per row
            const int col = idx & 31;
            float4 v = g[idx];
            *reinterpret_cast<float4*>(&sA[row][col * 4]) = v;
        }
        __syncthreads();

        // ====== phase 1: Q/K projection. thread = (row r, h-pair, BOTH mats) ======
        // agent LDS: quad-broadcast (free dedup). weight LDS: 4 distinct/warp (broadcast x8).
        // No shuffles, 4 accumulators (f32x2) per thread.
        {
            U64F2 aq0, aq1, ak0, ak1;
            aq0.u = aq1.u = ak0.u = ak1.u = 0ULL;

            #pragma unroll
            for (int k = 0; k < 32; k++) {
                const ulonglong2 s   = *reinterpret_cast<const ulonglong2*>(&sA[r][k * 4]);
                const ulonglong2 wq0 = *reinterpret_cast<const ulonglong2*>(&sW[0][h0][k * 4]);
                const ulonglong2 wq1 = *reinterpret_cast<const ulonglong2*>(&sW[0][h1][k * 4]);
                const ulonglong2 wk0 = *reinterpret_cast<const ulonglong2*>(&sW[1][h0][k * 4]);
                const ulonglong2 wk1 = *reinterpret_cast<const ulonglong2*>(&sW[1][h1][k * 4]);
                fma2(aq0.u, s.x, wq0.x); fma2(aq0.u, s.y, wq0.y);
                fma2(aq1.u, s.x, wq1.x); fma2(aq1.u, s.y, wq1.y);
                fma2(ak0.u, s.x, wk0.x); fma2(ak0.u, s.y, wk0.y);
                fma2(ak1.u, s.x, wk1.x); fma2(ak1.u, s.y, wk1.y);
            }
            const float q0v = aq0.f.x + aq0.f.y + sb[0][h0];
            const float q1v = aq1.f.x + aq1.f.y + sb[0][h1];
            const float k0v = ak0.f.x + ak0.f.y + sb[1][h0];
            const float k1v = ak1.f.x + ak1.f.y + sb[1][h1];
            *reinterpret_cast<float2*>(&qsm[r * HDIM + h0]) = make_float2(q0v, q1v);
            *reinterpret_cast<float2*>(&ksm[r * HDIM + h0]) = make_float2(k0v, k1v);
        }
        __syncthreads();

        // ====== phase 2: logits row r, cols [c*16, c*16+16), softmax, off-diag store ======
        {
            float qv[HDIM];
            {
                float4 qa = *reinterpret_cast<const float4*>(&qsm[r * HDIM]);
                float4 qb = *reinterpret_cast<const float4*>(&qsm[r * HDIM + 4]);
                qv[0]=qa.x; qv[1]=qa.y; qv[2]=qa.z; qv[3]=qa.w;
                qv[4]=qb.x; qv[5]=qb.y; qv[6]=qb.z; qv[7]=qb.w;
            }

            float a[16];
            #pragma unroll
            for (int i = 0; i < 16; i++) a[i] = 0.f;

            // att[r][x] = sum_h q[r][h] * kflat[h*64 + x]   (reshape semantics)
            #pragma unroll
            for (int h = 0; h < HDIM; h++) {
                const float qh = qv[h];
                #pragma unroll
                for (int j = 0; j < 4; j++) {
                    float4 kk = *reinterpret_cast<const float4*>(&ksm[h * ADIM + c * 16 + j * 4]);
                    a[4*j+0] += qh * kk.x;
                    a[4*j+1] += qh * kk.y;
                    a[4*j+2] += qh * kk.z;
                    a[4*j+3] += qh * kk.w;
                }
            }

            // softmax over 64 cols: 16 local + reduce across the 4 quad lanes
            float m = a[0];
            #pragma unroll
            for (int i = 1; i < 16; i++) m = fmaxf(m, a[i]);
            m = fmaxf(m, __shfl_xor_sync(0xffffffffu, m, 1));
            m = fmaxf(m, __shfl_xor_sync(0xffffffffu, m, 2));

            float ssum = 0.f;
            #pragma unroll
            for (int i = 0; i < 16; i++) { a[i] = __expf(a[i] - m); ssum += a[i]; }
            ssum += __shfl_xor_sync(0xffffffffu, ssum, 1);
            ssum += __shfl_xor_sync(0xffffffffu, ssum, 2);
            const float inv = __frcp_rn(ssum);

            const long long tb = tb0 + t;
            float* orow = out + (tb * ADIM + r) * (long long)(ADIM - 1);
            #pragma unroll
            for (int i = 0; i < 16; i++) {
                const int x = c * 16 + i;
                if (x != r) orow[x - (x > r ? 1 : 0)] = a[i] * inv;
            }
        }
        __syncthreads();   // qsm/ksm/sA reused next tile
    }
}

extern "C" void kernel_launch(void* const* d_in, const int* in_sizes, int n_in,
                              void* d_out, int out_size)
{
    const float* agent = (const float*)d_in[0];
    const float* Wq    = (const float*)d_in[1];
    const float* bq    = (const float*)d_in[2];
    const float* Wk    = (const float*)d_in[3];
    const float* bk    = (const float*)d_in[4];
    float* out = (float*)d_out;

    const int T = 512, B = 32;
    attn_fused_kernel<<<(T * B) / TLOOP, TPB>>>(agent, Wq, bq, Wk, bk, out);
}

// round 15
// speedup vs baseline: 1.6417x; 1.3056x over previous
#include <cuda_runtime.h>

// Problem constants (T=512, B=32, A=64, N=128, H=8)
#define TPB   256
#define ADIM  64
#define NDIM  128
#define HDIM  8
#define TILES 2     // (t,b) pairs per block: halves acc regs vs TILES=4 -> occ 4 blocks/SM

__global__ __launch_bounds__(TPB, 4)
void attn_fused_kernel(const float* __restrict__ agent,
                       const float* __restrict__ Wq, const float* __restrict__ bq,
                       const float* __restrict__ Wk, const float* __restrict__ bk,
                       float* __restrict__ out)
{
    __shared__ float sWq[HDIM][NDIM];       // transposed: sWq[h][n]
    __shared__ float sWk[HDIM][NDIM];
    __shared__ float sb[2][HDIM];           // [0]=bq, [1]=bk
    __shared__ float qsm[TILES][ADIM * HDIM];   // q[a][h] at a*8+h
    __shared__ float ksm[TILES][ADIM * HDIM];   // k flat row-major; att reads ksm[h*64+a]

    const int tid = threadIdx.x;
    const long long tb0 = (long long)blockIdx.x * TILES;

    // ---- weights (transposed) + biases into smem ----
    for (int i = tid; i < NDIM * HDIM; i += TPB) {
        int n = i >> 3, h = i & 7;
        sWq[h][n] = Wq[i];
        sWk[h][n] = Wk[i];
    }
    if (tid < HDIM)        sb[0][tid] = bq[tid];
    else if (tid < 2*HDIM) sb[1][tid - HDIM] = bk[tid - HDIM];
    __syncthreads();

    // =========== phase 1: fused Q/K projection for 2 tiles ===========
    // thread = (row, N-quarter); agent read ONCE from global (coalesced LDG.128),
    // weight LDS amortized over 2 register-held tiles. acc[2][16] = 32 regs.
    {
        const int r = tid >> 2;   // agent row 0..63
        const int c = tid & 3;    // chunk within row

        const float4* srow[TILES];
        #pragma unroll
        for (int t = 0; t < TILES; t++)
            srow[t] = reinterpret_cast<const float4*>(
                agent + (tb0 + t) * (long long)(ADIM * NDIM) + (long long)r * NDIM);

        float accq[TILES][HDIM], acck[TILES][HDIM];
        #pragma unroll
        for (int t = 0; t < TILES; t++)
            #pragma unroll
            for (int h = 0; h < HDIM; h++) { accq[t][h] = 0.f; acck[t][h] = 0.f; }

        #pragma unroll
        for (int k = 0; k < 8; k++) {
            float4 s[TILES];
            #pragma unroll
            for (int t = 0; t < TILES; t++) s[t] = srow[t][c + 4 * k];

            const int nb = (c + 4 * k) * 4;
            #pragma unroll
            for (int h = 0; h < HDIM; h++) {
                const float4 wq = *reinterpret_cast<const float4*>(&sWq[h][nb]);
                const float4 wk = *reinterpret_cast<const float4*>(&sWk[h][nb]);
                #pragma unroll
                for (int t = 0; t < TILES; t++) {
                    accq[t][h] += s[t].x * wq.x + s[t].y * wq.y + s[t].z * wq.z + s[t].w * wq.w;
                    acck[t][h] += s[t].x * wk.x + s[t].y * wk.y + s[t].z * wk.z + s[t].w * wk.w;
                }
            }
        }

        // Halving butterfly across the 4 lanes of this row (each lane has an N-quarter).
        // Stage 1 (xor 1): even lane keeps q-sums, odd keeps k-sums.
        // Stage 2 (xor 2): bit1 picks h-half. Each lane finally owns 4 (mat,h) values.
        const int matk  = c & 1;
        const int hbase = (c & 2) ? 4 : 0;
        #pragma unroll
        for (int t = 0; t < TILES; t++) {
            float v[HDIM];
            #pragma unroll
            for (int h = 0; h < HDIM; h++) {
                float sent = matk ? accq[t][h] : acck[t][h];
                float recv = __shfl_xor_sync(0xffffffffu, sent, 1);
                v[h] = (matk ? acck[t][h] : accq[t][h]) + recv;
            }
            float f[4];
            #pragma unroll
            for (int i = 0; i < 4; i++) {
                float sent = (c & 2) ? v[i] : v[i + 4];
                float recv = __shfl_xor_sync(0xffffffffu, sent, 2);
                f[i] = ((c & 2) ? v[i + 4] : v[i]) + recv;
            }
            float* dst = matk ? ksm[t] : qsm[t];
            #pragma unroll
            for (int i = 0; i < 4; i++)
                dst[r * HDIM + hbase + i] = f[i] + sb[matk][hbase + i];
        }
    }
    __syncthreads();

    // =========== phase 2: logits + softmax + off-diag store ===========
    // thread = (row-pair, 8-column chunk): k-tile LDS shared across 2 rows
    {
        const int rp = tid >> 3;        // 0..31
        const int cc = tid & 7;         // column chunk 0..7
        const int r0 = rp * 2, r1 = r0 + 1;

        #pragma unroll
        for (int t = 0; t < TILES; t++) {
            float q0[HDIM], q1[HDIM];
            {
                float4 a = *reinterpret_cast<const float4*>(&qsm[t][r0 * HDIM]);
                float4 b = *reinterpret_cast<const float4*>(&qsm[t][r0 * HDIM + 4]);
                q0[0]=a.x; q0[1]=a.y; q0[2]=a.z; q0[3]=a.w;
                q0[4]=b.x; q0[5]=b.y; q0[6]=b.z; q0[7]=b.w;
                float4 e = *reinterpret_cast<const float4*>(&qsm[t][r1 * HDIM]);
                float4 d = *reinterpret_cast<const float4*>(&qsm[t][r1 * HDIM + 4]);
                q1[0]=e.x; q1[1]=e.y; q1[2]=e.z; q1[3]=e.w;
                q1[4]=d.x; q1[5]=d.y; q1[6]=d.z; q1[7]=d.w;
            }

            float a0[8], a1[8];
            #pragma unroll
            for (int i = 0; i < 8; i++) { a0[i] = 0.f; a1[i] = 0.f; }

            // att[r][a] = sum_h q[r][h] * kflat[h*64 + a]  (reshape semantics)
            #pragma unroll
            for (int h = 0; h < HDIM; h++) {
                const float4 ka = *reinterpret_cast<const float4*>(&ksm[t][h * ADIM + cc * 8]);
                const float4 kb = *reinterpret_cast<const float4*>(&ksm[t][h * ADIM + cc * 8 + 4]);
                const float x0 = q0[h], x1 = q1[h];
                a0[0] += x0 * ka.x; a0[1] += x0 * ka.y; a0[2] += x0 * ka.z; a0[3] += x0 * ka.w;
                a0[4] += x0 * kb.x; a0[5] += x0 * kb.y; a0[6] += x0 * kb.z; a0[7] += x0 * kb.w;
                a1[0] += x1 * ka.x; a1[1] += x1 * ka.y; a1[2] += x1 * ka.z; a1[3] += x1 * ka.w;
                a1[4] += x1 * kb.x; a1[5] += x1 * kb.y; a1[6] += x1 * kb.z; a1[7] += x1 * kb.w;
            }

            // softmax over 64 cols: 8 local + reduce over the 8 lanes of this row-pair
            float m0 = a0[0], m1 = a1[0];
            #pragma unroll
            for (int i = 1; i < 8; i++) { m0 = fmaxf(m0, a0[i]); m1 = fmaxf(m1, a1[i]); }
            #pragma unroll
            for (int s = 1; s < 8; s <<= 1) {
                m0 = fmaxf(m0, __shfl_xor_sync(0xffffffffu, m0, s));
                m1 = fmaxf(m1, __shfl_xor_sync(0xffffffffu, m1, s));
            }
            float s0 = 0.f, s1 = 0.f;
            #pragma unroll
            for (int i = 0; i < 8; i++) {
                a0[i] = __expf(a0[i] - m0); s0 += a0[i];
                a1[i] = __expf(a1[i] - m1); s1 += a1[i];
            }
            #pragma unroll
            for (int s = 1; s < 8; s <<= 1) {
                s0 += __shfl_xor_sync(0xffffffffu, s0, s);
                s1 += __shfl_xor_sync(0xffffffffu, s1, s);
            }
            const float inv0 = __frcp_rn(s0);
            const float inv1 = __frcp_rn(s1);

            // off-diagonal gather store: col a -> a (a<r) / a-1 (a>r), skip a==r
            const long long tb = tb0 + t;
            float* o0 = out + (tb * ADIM + r0) * (long long)(ADIM - 1);
            float* o1 = out + (tb * ADIM + r1) * (long long)(ADIM - 1);
            #pragma unroll
            for (int i = 0; i < 8; i++) {
                const int a = cc * 8 + i;
                if (a != r0) o0[a - (a > r0 ? 1 : 0)] = a0[i] * inv0;
                if (a != r1) o1[a - (a > r1 ? 1 : 0)] = a1[i] * inv1;
            }
        }
    }
}

extern "C" void kernel_launch(void* const* d_in, const int* in_sizes, int n_in,
                              void* d_out, int out_size)
{
    const float* agent = (const float*)d_in[0];
    const float* Wq    = (const float*)d_in[1];
    const float* bq    = (const float*)d_in[2];
    const float* Wk    = (const float*)d_in[3];
    const float* bk    = (const float*)d_in[4];
    float* out = (float*)d_out;

    const int T = 512, B = 32;
    attn_fused_kernel<<<(T * B) / TILES, TPB>>>(agent, Wq, bq, Wk, bk, out);
}

// round 16
// speedup vs baseline: 1.8007x; 1.0969x over previous
#include <cuda_runtime.h>

// Problem constants (T=512, B=32, A=64, N=128, H=8)
#define TPB   256
#define ADIM  64
#define NDIM  128
#define HDIM  8
#define TILES 2

typedef unsigned long long u64;

__device__ __forceinline__ void fma2(u64& d, u64 a, u64 b) {
    // packed fp32x2 FMA (sm_103a); per-lane RN == scalar FFMA results
    asm("fma.rn.f32x2 %0, %1, %2, %0;" : "+l"(d) : "l"(a), "l"(b));
}
__device__ __forceinline__ u64 dup2(float x) {
    u64 r; asm("mov.b64 %0, {%1, %1};" : "=l"(r) : "f"(x)); return r;
}
union U64F2 { u64 u; float2 f; };

__global__ __launch_bounds__(TPB, 4)
void attn_fused_kernel(const float* __restrict__ agent,
                       const float* __restrict__ Wq, const float* __restrict__ bq,
                       const float* __restrict__ Wk, const float* __restrict__ bk,
                       float* __restrict__ out)
{
    // sW2[m][hp][n] = (W[n][2hp], W[n][2hp+1]) packed as one u64 -> h-pair FMA2
    __shared__ u64   sW2[2][4][NDIM];
    __shared__ float sb[2][HDIM];
    __shared__ float qsm[TILES][ADIM * HDIM];   // q[a][h] at a*8+h
    __shared__ float ksm[TILES][ADIM * HDIM];   // k flat row-major; att reads ksm[h*64+a]

    const int tid = threadIdx.x;
    const long long tb0 = (long long)blockIdx.x * TILES;

    // ---- weights: h-pairs are adjacent in row-major (N,H) source -> direct u64 copy ----
    {
        const u64* q64 = reinterpret_cast<const u64*>(Wq);
        const u64* k64 = reinterpret_cast<const u64*>(Wk);
        for (int i = tid; i < 4 * NDIM; i += TPB) {   // 512 u64 per matrix
            const int n = i >> 2, hp = i & 3;
            sW2[0][hp][n] = q64[n * 4 + hp];
            sW2[1][hp][n] = k64[n * 4 + hp];
        }
    }
    if (tid < HDIM)        sb[0][tid] = bq[tid];
    else if (tid < 2*HDIM) sb[1][tid - HDIM] = bk[tid - HDIM];
    __syncthreads();

    // =========== phase 1: fused Q/K projection, h-pair-packed FMA2 ===========
    {
        const int r = tid >> 2;   // agent row 0..63
        const int c = tid & 3;    // N-quarter chunk

        const float4* srow[TILES];
        #pragma unroll
        for (int t = 0; t < TILES; t++)
            srow[t] = reinterpret_cast<const float4*>(
                agent + (tb0 + t) * (long long)(ADIM * NDIM) + (long long)r * NDIM);

        U64F2 acc[2][TILES][4];   // [mat][tile][hp] : lanes = (h=2hp, h=2hp+1)
        #pragma unroll
        for (int m = 0; m < 2; m++)
            #pragma unroll
            for (int t = 0; t < TILES; t++)
                #pragma unroll
                for (int hp = 0; hp < 4; hp++) acc[m][t][hp].u = 0ULL;

        #pragma unroll
        for (int k = 0; k < 8; k++) {
            float4 s[TILES];
            #pragma unroll
            for (int t = 0; t < TILES; t++) s[t] = srow[t][c + 4 * k];

            u64 sd[TILES][4];
            #pragma unroll
            for (int t = 0; t < TILES; t++) {
                sd[t][0] = dup2(s[t].x); sd[t][1] = dup2(s[t].y);
                sd[t][2] = dup2(s[t].z); sd[t][3] = dup2(s[t].w);
            }

            const int nb = (c + 4 * k) * 4;   // n-index base (4 n per chunk)
            #pragma unroll
            for (int m = 0; m < 2; m++) {
                #pragma unroll
                for (int hp = 0; hp < 4; hp++) {
                    const ulonglong2 w01 = *reinterpret_cast<const ulonglong2*>(&sW2[m][hp][nb]);
                    const ulonglong2 w23 = *reinterpret_cast<const ulonglong2*>(&sW2[m][hp][nb + 2]);
                    #pragma unroll
                    for (int t = 0; t < TILES; t++) {
                        fma2(acc[m][t][hp].u, sd[t][0], w01.x);
                        fma2(acc[m][t][hp].u, sd[t][1], w01.y);
                        fma2(acc[m][t][hp].u, sd[t][2], w23.x);
                        fma2(acc[m][t][hp].u, sd[t][3], w23.y);
                    }
                }
            }
        }

        // Halving butterfly across the 4 lanes of this row (lane = N-quarter).
        // Stage 1 (xor 1): even lane keeps q, odd keeps k. Stage 2 (xor 2): bit1 picks h-half.
        const int matk  = c & 1;
        const int hbase = (c & 2) ? 4 : 0;
        #pragma unroll
        for (int t = 0; t < TILES; t++) {
            float accq[HDIM], acck[HDIM];
            #pragma unroll
            for (int hp = 0; hp < 4; hp++) {
                accq[2*hp]   = acc[0][t][hp].f.x;  accq[2*hp+1] = acc[0][t][hp].f.y;
                acck[2*hp]   = acc[1][t][hp].f.x;  acck[2*hp+1] = acc[1][t][hp].f.y;
            }
            float v[HDIM];
            #pragma unroll
            for (int h = 0; h < HDIM; h++) {
                float sent = matk ? accq[h] : acck[h];
                float recv = __shfl_xor_sync(0xffffffffu, sent, 1);
                v[h] = (matk ? acck[h] : accq[h]) + recv;
            }
            float f[4];
            #pragma unroll
            for (int i = 0; i < 4; i++) {
                float sent = (c & 2) ? v[i] : v[i + 4];
                float recv = __shfl_xor_sync(0xffffffffu, sent, 2);
                f[i] = ((c & 2) ? v[i + 4] : v[i]) + recv;
            }
            float* dst = matk ? ksm[t] : qsm[t];
            #pragma unroll
            for (int i = 0; i < 4; i++)
                dst[r * HDIM + hbase + i] = f[i] + sb[matk][hbase + i];
        }
    }
    __syncthreads();

    // =========== phase 2: logits (column-pair FMA2) + softmax + off-diag store ===========
    {
        const int rp = tid >> 3;        // 0..31
        const int cc = tid & 7;         // column chunk 0..7
        const int r0 = rp * 2, r1 = r0 + 1;

        #pragma unroll
        for (int t = 0; t < TILES; t++) {
            float q0[HDIM], q1[HDIM];
            {
                float4 a = *reinterpret_cast<const float4*>(&qsm[t][r0 * HDIM]);
                float4 b = *reinterpret_cast<const float4*>(&qsm[t][r0 * HDIM + 4]);
                q0[0]=a.x; q0[1]=a.y; q0[2]=a.z; q0[3]=a.w;
                q0[4]=b.x; q0[5]=b.y; q0[6]=b.z; q0[7]=b.w;
                float4 e = *reinterpret_cast<const float4*>(&qsm[t][r1 * HDIM]);
                float4 d = *reinterpret_cast<const float4*>(&qsm[t][r1 * HDIM + 4]);
                q1[0]=e.x; q1[1]=e.y; q1[2]=e.z; q1[3]=e.w;
                q1[4]=d.x; q1[5]=d.y; q1[6]=d.z; q1[7]=d.w;
            }

            U64F2 a0[4], a1[4];   // 8 columns per row as 4 packed pairs
            #pragma unroll
            for (int j = 0; j < 4; j++) { a0[j].u = 0ULL; a1[j].u = 0ULL; }

            // att[r][x] = sum_h q[r][h] * kflat[h*64 + x]  (reshape semantics)
            #pragma unroll
            for (int h = 0; h < HDIM; h++) {
                const ulonglong2 ka = *reinterpret_cast<const ulonglong2*>(&ksm[t][h * ADIM + cc * 8]);
                const ulonglong2 kb = *reinterpret_cast<const ulonglong2*>(&ksm[t][h * ADIM + cc * 8 + 4]);
                const u64 d0 = dup2(q0[h]);
                const u64 d1 = dup2(q1[h]);
                fma2(a0[0].u, d0, ka.x); fma2(a0[1].u, d0, ka.y);
                fma2(a0[2].u, d0, kb.x); fma2(a0[3].u, d0, kb.y);
                fma2(a1[0].u, d1, ka.x); fma2(a1[1].u, d1, ka.y);
                fma2(a1[2].u, d1, kb.x); fma2(a1[3].u, d1, kb.y);
            }

            // softmax over 64 cols: 8 local + reduce over the 8 lanes of this row-pair
            float m0 = fmaxf(a0[0].f.x, a0[0].f.y);
            float m1 = fmaxf(a1[0].f.x, a1[0].f.y);
            #pragma unroll
            for (int j = 1; j < 4; j++) {
                m0 = fmaxf(m0, fmaxf(a0[j].f.x, a0[j].f.y));
                m1 = fmaxf(m1, fmaxf(a1[j].f.x, a1[j].f.y));
            }
            #pragma unroll
            for (int s = 1; s < 8; s <<= 1) {
                m0 = fmaxf(m0, __shfl_xor_sync(0xffffffffu, m0, s));
                m1 = fmaxf(m1, __shfl_xor_sync(0xffffffffu, m1, s));
            }
            float e0[8], e1[8];
            float s0 = 0.f, s1 = 0.f;
            #pragma unroll
            for (int j = 0; j < 4; j++) {
                e0[2*j]   = __expf(a0[j].f.x - m0);  s0 += e0[2*j];
                e0[2*j+1] = __expf(a0[j].f.y - m0);  s0 += e0[2*j+1];
                e1[2*j]   = __expf(a1[j].f.x - m1);  s1 += e1[2*j];
                e1[2*j+1] = __expf(a1[j].f.y - m1);  s1 += e1[2*j+1];
            }
            #pragma unroll
            for (int s = 1; s < 8; s <<= 1) {
                s0 += __shfl_xor_sync(0xffffffffu, s0, s);
                s1 += __shfl_xor_sync(0xffffffffu, s1, s);
            }
            const float inv0 = __frcp_rn(s0);
            const float inv1 = __frcp_rn(s1);

            // off-diagonal gather store: col x -> x (x<r) / x-1 (x>r), skip x==r
            const long long tb = tb0 + t;
            float* o0 = out + (tb * ADIM + r0) * (long long)(ADIM - 1);
            float* o1 = out + (tb * ADIM + r1) * (long long)(ADIM - 1);
            #pragma unroll
            for (int i = 0; i < 8; i++) {
                const int x = cc * 8 + i;
                if (x != r0) o0[x - (x > r0 ? 1 : 0)] = e0[i] * inv0;
                if (x != r1) o1[x - (x > r1 ? 1 : 0)] = e1[i] * inv1;
            }
        }
    }
}

extern "C" void kernel_launch(void* const* d_in, const int* in_sizes, int n_in,
                              void* d_out, int out_size)
{
    const float* agent = (const float*)d_in[0];
    const float* Wq    = (const float*)d_in[1];
    const float* bq    = (const float*)d_in[2];
    const float* Wk    = (const float*)d_in[3];
    const float* bk    = (const float*)d_in[4];
    float* out = (float*)d_out;

    const int T = 512, B = 32;
    attn_fused_kernel<<<(T * B) / TILES, TPB>>>(agent, Wq, bq, Wk, bk, out);
}